// round 1
// baseline (speedup 1.0000x reference)
#include <cuda_runtime.h>
#include <cstdint>

// ---------------- problem constants ----------------
#define SQ    4096          // sequence length
#define EMBD  256
#define HDIRD 256           // HID/2
#define NG    1024          // 4*HDIR
#define TAGS  10
#define NEGV  -10000.0f
#define CL    8             // cluster size per direction

// ---------------- scratch (device globals; no dynamic alloc) ----------------
__device__ float g_x[SQ * EMBD];              // gathered embeddings   4 MB
__device__ float g_xw[2][SQ * NG];            // input-gate precompute 32 MB
__device__ float g_h[2][SQ * HDIRD];          // hidden states         8 MB
__device__ float g_feats[SQ * TAGS];          // CRF emission feats

// ---------------- helpers ----------------
__device__ __forceinline__ uint32_t smem_u32(const void* p) {
    return (uint32_t)__cvta_generic_to_shared(p);
}
__device__ __forceinline__ void st_cluster_f32(uint32_t laddr, uint32_t rank, float v) {
    uint32_t rem;
    asm volatile("mapa.shared::cluster.u32 %0, %1, %2;" : "=r"(rem) : "r"(laddr), "r"(rank));
    asm volatile("st.shared::cluster.f32 [%0], %1;" :: "r"(rem), "f"(v) : "memory");
}
#define CLUSTER_SYNC_() do {                                                   \
    asm volatile("barrier.cluster.arrive.aligned;" ::: "memory");              \
    asm volatile("barrier.cluster.wait.aligned;"   ::: "memory");              \
} while (0)

__device__ __forceinline__ float sigm_f(float x) {
    return 1.0f / (1.0f + __expf(-x));
}
__device__ __forceinline__ float tanh_f(float x) {
    // overflow-safe tanh via exp of negative argument
    float e = __expf(-2.0f * fabsf(x));
    float r = (1.0f - e) / (1.0f + e);
    return copysignf(r, x);
}

// ---------------- kernel 1: embedding gather ----------------
__global__ void gather_k(const int* __restrict__ sent, const float* __restrict__ emb) {
    int gid = blockIdx.x * blockDim.x + threadIdx.x;  // over SQ*64 float4
    int row = gid >> 6;
    int c   = gid & 63;
    ((float4*)g_x)[row * 64 + c] =
        ((const float4*)emb)[(size_t)sent[row] * 64 + c];
}

// ---------------- kernel 2: xw = x @ Wih^T + (bih+bhh), both directions ----------------
// tile 64(s) x 64(j), K=EMBD, 256 threads, 4x4 microtile
__global__ void xw_gemm_k(const float* __restrict__ Wf, const float* __restrict__ Wb,
                          const float* __restrict__ bihf, const float* __restrict__ bhhf,
                          const float* __restrict__ bihb, const float* __restrict__ bhhb) {
    int d = blockIdx.z;
    const float* W  = d ? Wb : Wf;
    const float* b1 = d ? bihb : bihf;
    const float* b2 = d ? bhhb : bhhf;

    __shared__ float As[32][65];
    __shared__ float Bs[32][65];

    int s0 = blockIdx.x * 64;
    int j0 = blockIdx.y * 64;
    int tid = threadIdx.x;
    int tx = tid & 15, ty = tid >> 4;

    float acc[4][4];
#pragma unroll
    for (int i = 0; i < 4; i++)
#pragma unroll
        for (int j = 0; j < 4; j++) acc[i][j] = 0.0f;

    for (int k0 = 0; k0 < EMBD; k0 += 32) {
#pragma unroll
        for (int i = 0; i < 8; i++) {
            int idx = i * 256 + tid;
            int si = idx >> 5, e = idx & 31;
            As[e][si] = g_x[(s0 + si) * EMBD + k0 + e];
            Bs[e][si] = W[(j0 + si) * EMBD + k0 + e];
        }
        __syncthreads();
#pragma unroll
        for (int e = 0; e < 32; e++) {
            float a[4], bb[4];
#pragma unroll
            for (int i = 0; i < 4; i++) { a[i] = As[e][ty * 4 + i]; bb[i] = Bs[e][tx * 4 + i]; }
#pragma unroll
            for (int i = 0; i < 4; i++)
#pragma unroll
                for (int j = 0; j < 4; j++) acc[i][j] = fmaf(a[i], bb[j], acc[i][j]);
        }
        __syncthreads();
    }
#pragma unroll
    for (int i = 0; i < 4; i++)
#pragma unroll
        for (int j = 0; j < 4; j++) {
            int jj = j0 + tx * 4 + j;
            g_xw[d][(s0 + ty * 4 + i) * NG + jj] = acc[i][j] + b1[jj] + b2[jj];
        }
}

// ---------------- kernel 3: recurrent LSTM, one 8-CTA cluster per direction ----------------
// CTA rank r owns h chunk [r*32, r*32+32) and the 4*32 = 128 corresponding Whh rows,
// held in registers (float4 Wreg[32] per thread; 2 threads per row).
__global__ void __cluster_dims__(CL, 1, 1) __launch_bounds__(256, 1)
lstm_k(const float* __restrict__ Whhf, const float* __restrict__ Whhb) {
    int dir = blockIdx.y;
    const float* Whh = dir ? Whhb : Whhf;
    const float* xw  = g_xw[dir];
    int r   = blockIdx.x;           // cluster rank (cluster spans x)
    int tid = threadIdx.x;
    int rr   = tid >> 1;            // 0..127 local row
    int half = tid & 1;             // column half (0..127 / 128..255)
    int gate = rr >> 5;
    int j5   = rr & 31;
    int grow = gate * HDIRD + r * 32 + j5;   // global Whh row / xw column

    // weights -> registers
    float4 Wreg[32];
    const float4* wsrc = (const float4*)(Whh + (size_t)grow * HDIRD + half * 128);
#pragma unroll
    for (int k = 0; k < 32; k++) Wreg[k] = wsrc[k];

    __shared__ __align__(16) float hbuf[2][256];
    __shared__ float zbuf[128];
    hbuf[0][tid] = 0.0f;
    hbuf[1][tid] = 0.0f;

    float c = 0.0f;
    float xwreg = 0.0f;
    int pos0 = dir ? (SQ - 1) : 0;
    if (!half) xwreg = xw[(size_t)pos0 * NG + grow];

    CLUSTER_SYNC_();   // hbuf init visible cluster-wide

    for (int t = 0; t < SQ; t++) {
        int p = t & 1;
        const float4* h4 = (const float4*)(&hbuf[p][half * 128]);
        float4 a = make_float4(0.f, 0.f, 0.f, 0.f);
#pragma unroll
        for (int k = 0; k < 32; k++) {
            float4 hv = h4[k];
            a.x = fmaf(Wreg[k].x, hv.x, a.x);
            a.y = fmaf(Wreg[k].y, hv.y, a.y);
            a.z = fmaf(Wreg[k].z, hv.z, a.z);
            a.w = fmaf(Wreg[k].w, hv.w, a.w);
        }
        float acc = (a.x + a.y) + (a.z + a.w);
        acc += __shfl_xor_sync(0xffffffffu, acc, 1);
        if (!half) zbuf[rr] = acc + xwreg;

        // prefetch next step's xw while this step finishes
        int tn = t + 1;
        if (!half && tn < SQ) {
            int pos = dir ? (SQ - 1 - tn) : tn;
            xwreg = xw[(size_t)pos * NG + grow];
        }
        __syncthreads();

        if (tid < 32) {
            float zi = zbuf[tid], zf = zbuf[32 + tid], zg = zbuf[64 + tid], zo = zbuf[96 + tid];
            float ig = sigm_f(zi);
            float fg = sigm_f(zf);
            float gg = tanh_f(zg);
            float og = sigm_f(zo);
            c = fmaf(fg, c, ig * gg);
            float hn = og * tanh_f(c);

            int pos = dir ? (SQ - 1 - t) : t;
            g_h[dir][(size_t)pos * HDIRD + r * 32 + tid] = hn;

            uint32_t la = smem_u32(&hbuf[p ^ 1][r * 32 + tid]);
#pragma unroll
            for (int rk = 0; rk < CL; rk++) st_cluster_f32(la, rk, hn);
        }
        CLUSTER_SYNC_();   // h broadcast visible; also separates zbuf reuse
    }
}

// ---------------- kernel 4: feats = [h_f | h_b] @ Wout^T + b ----------------
__global__ void feats_k(const float* __restrict__ Wout, const float* __restrict__ bout) {
    __shared__ float Wsm[TAGS][512];
    __shared__ float bsm[TAGS];
    int tid = threadIdx.x;
    for (int i = tid; i < TAGS * 512; i += 256) Wsm[i / 512][i % 512] = Wout[i];
    if (tid < TAGS) bsm[tid] = bout[tid];
    __syncthreads();

    int s = blockIdx.x * 256 + tid;
    float acc[TAGS];
#pragma unroll
    for (int t = 0; t < TAGS; t++) acc[t] = bsm[t];
    for (int k = 0; k < HDIRD; k++) {
        float x = g_h[0][(size_t)s * HDIRD + k];
#pragma unroll
        for (int t = 0; t < TAGS; t++) acc[t] = fmaf(x, Wsm[t][k], acc[t]);
    }
    for (int k = 0; k < HDIRD; k++) {
        float x = g_h[1][(size_t)s * HDIRD + k];
#pragma unroll
        for (int t = 0; t < TAGS; t++) acc[t] = fmaf(x, Wsm[t][256 + k], acc[t]);
    }
#pragma unroll
    for (int t = 0; t < TAGS; t++) g_feats[s * TAGS + t] = acc[t];
}

// ---------------- kernel 5: Viterbi decode (single warp) ----------------
__global__ void viterbi_k(const float* __restrict__ trans, float* __restrict__ out,
                          int out_size) {
    __shared__ unsigned char bp[SQ][TAGS];   // 40 KB backpointers
    int n = threadIdx.x;                     // 32 lanes, 10 active

    float tr[TAGS];
#pragma unroll
    for (int p = 0; p < TAGS; p++) tr[p] = (n < TAGS) ? trans[n * TAGS + p] : NEGV;

    float fvr = (n == 8) ? 0.0f : NEGV;      // START = 8
    float fa = (n < TAGS) ? g_feats[0 * TAGS + n] : 0.0f;
    float fb = (n < TAGS) ? g_feats[1 * TAGS + n] : 0.0f;

    for (int t = 0; t < SQ; t++) {
        float m = -3.4e38f;
        int bi = 0;
#pragma unroll
        for (int p = 0; p < TAGS; p++) {
            float v = __shfl_sync(0xffffffffu, fvr, p) + tr[p];
            if (v > m) { m = v; bi = p; }    // strict > keeps first max (jnp.argmax)
        }
        if (n < TAGS) bp[t][n] = (unsigned char)bi;
        float nf = m + fa;
        fa = fb;
        int tn = t + 2;
        if (n < TAGS && tn < SQ) fb = g_feats[tn * TAGS + n];
        fvr = nf;
    }

    // terminal = fv + trans[STOP=9]
    float term = fvr + ((n < TAGS) ? trans[9 * TAGS + n] : NEGV);
    float bm = -3.4e38f;
    int bidx = 0;
#pragma unroll
    for (int p = 0; p < TAGS; p++) {
        float v = __shfl_sync(0xffffffffu, term, p);
        if (v > bm) { bm = v; bidx = p; }
    }
    if (n == 0) {
        int off = (out_size > SQ) ? 1 : 0;
        if (off) out[0] = bm;                // score first, then path
        int tag = bidx;
        for (int t = SQ - 1; t >= 0; t--) {
            out[off + t] = (float)tag;
            tag = bp[t][tag];
        }
    }
}

// ---------------- launch ----------------
extern "C" void kernel_launch(void* const* d_in, const int* in_sizes, int n_in,
                              void* d_out, int out_size) {
    const int*   sent  = (const int*)d_in[0];
    const float* emb   = (const float*)d_in[1];
    const float* Wih_f = (const float*)d_in[2];
    const float* Whh_f = (const float*)d_in[3];
    const float* bih_f = (const float*)d_in[4];
    const float* bhh_f = (const float*)d_in[5];
    const float* Wih_b = (const float*)d_in[6];
    const float* Whh_b = (const float*)d_in[7];
    const float* bih_b = (const float*)d_in[8];
    const float* bhh_b = (const float*)d_in[9];
    const float* W_out = (const float*)d_in[10];
    const float* b_out = (const float*)d_in[11];
    const float* trans = (const float*)d_in[12];
    float* out = (float*)d_out;

    gather_k<<<(SQ * 64) / 256, 256>>>(sent, emb);
    xw_gemm_k<<<dim3(SQ / 64, NG / 64, 2), 256>>>(Wih_f, Wih_b, bih_f, bhh_f, bih_b, bhh_b);
    lstm_k<<<dim3(CL, 2, 1), 256>>>(Whh_f, Whh_b);
    feats_k<<<SQ / 256, 256>>>(W_out, b_out);
    viterbi_k<<<1, 32>>>(trans, out, out_size);
}